// round 1
// baseline (speedup 1.0000x reference)
#include <cuda_runtime.h>
#include <cstdint>

// ---------------- problem constants ----------------
#define TOK_LABEL   2
#define ACT_START   5
#define TIME_START  69
#define NB          8
#define NT_SEQ      2048
#define ND          1024
#define N_ACT       64
#define N_TIME      32
#define N_COLS      96            // 64 act + 32 time combined
#define M_TOT       (NB * NT_SEQ) // 16384
#define ACT_ELEMS   ((size_t)M_TOT * N_ACT)   // offset of time logits in d_out

// ---------------- scratch (no cudaMalloc allowed) ----------------
__device__ float g_Wc[N_COLS * ND];   // combined weights [96][1024]
__device__ float g_bc[N_COLS];        // combined bias
__device__ int   g_qlist[NB][NT_SEQ];
__device__ int   g_klist[NB][NT_SEQ];
__device__ int   g_kcls [NB][NT_SEQ]; // combined class column 0..95
__device__ int   g_qcnt[NB];
__device__ int   g_kcnt[NB];

// ---------------- helpers ----------------
__device__ __forceinline__ float softplus_f(float x) {
    return (x > 20.0f) ? x : log1pf(expf(x));
}

__device__ __forceinline__ unsigned long long pack2(float x, float y) {
    unsigned long long r;
    asm("mov.b64 %0, {%1,%2};" : "=l"(r) : "f"(x), "f"(y));
    return r;
}
__device__ __forceinline__ float2 unpack2(unsigned long long v) {
    float2 r;
    asm("mov.b64 {%0,%1}, %2;" : "=f"(r.x), "=f"(r.y) : "l"(v));
    return r;
}
// packed dual-FMA: d = a*b + d  (two f32 lanes per instruction)
__device__ __forceinline__ void fma2(unsigned long long& d,
                                     unsigned long long a,
                                     unsigned long long b) {
    asm("fma.rn.f32x2 %0, %1, %2, %0;" : "+l"(d) : "l"(a), "l"(b));
}

// ---------------- kernel 1: fold tied-embedding slices into weights ----------------
__global__ void wc_kernel(const float* __restrict__ E,
                          const float* __restrict__ Wn, const float* __restrict__ bn,
                          const float* __restrict__ Wt, const float* __restrict__ bt,
                          const float* __restrict__ tsa, const float* __restrict__ tst) {
    int i = blockIdx.x * blockDim.x + threadIdx.x;
    float sa = softplus_f(*tsa);
    float st = softplus_f(*tst);
    if (i < N_COLS * ND) {
        int r = i >> 10;       // combined row 0..95
        int c = i & (ND - 1);
        float v;
        if (r < N_ACT)
            v = Wn[r * ND + c] + sa * E[(ACT_START + r) * ND + c];
        else
            v = Wt[(r - N_ACT) * ND + c] + st * E[(TIME_START + (r - N_ACT)) * ND + c];
        g_Wc[i] = v;
    }
    if (i < N_COLS)
        g_bc[i] = (i < N_ACT) ? bn[i] : bt[i - N_ACT];
}

// ---------------- kernel 2: build query/key lists with warp ballots ----------------
__global__ void scan_kernel(const int* __restrict__ tokens) {
    int b    = blockIdx.x;
    int lane = threadIdx.x & 31;
    int warp = threadIdx.x >> 5;
    const int* tk = tokens + b * NT_SEQ;

    if (warp == 0) {          // queries: token == <LABEL>
        int cnt = 0;
        for (int base = 0; base < NT_SEQ; base += 32) {
            int pos = base + lane;
            bool p = (tk[pos] == TOK_LABEL);
            unsigned m = __ballot_sync(0xffffffffu, p);
            if (p) g_qlist[b][cnt + __popc(m & ((1u << lane) - 1u))] = pos;
            cnt += __popc(m);
        }
        if (lane == 0) g_qcnt[b] = cnt;
    } else if (warp == 1) {   // value keys: prev token == <LABEL>, token in class range
        int cnt = 0;
        for (int base = 0; base < NT_SEQ; base += 32) {
            int pos = base + lane;
            int tok = tk[pos];
            bool p = (pos >= 1) && (tk[pos - 1] == TOK_LABEL) && (tok >= ACT_START);
            unsigned m = __ballot_sync(0xffffffffu, p);
            if (p) {
                int r = cnt + __popc(m & ((1u << lane) - 1u));
                g_klist[b][r] = pos;
                g_kcls[b][r]  = (tok < TIME_START) ? (tok - ACT_START)
                                                   : (N_ACT + (tok - TIME_START));
            }
            cnt += __popc(m);
        }
        if (lane == 0) g_kcnt[b] = cnt;
    }
}

// ---------------- kernel 3: the 16384x96x1024 fp32 GEMM (f32x2 packed) ----------------
#define BM 64
#define BK 32
#define SA 65   // As row stride (k-major), 65 -> conflict-free transposed stores
#define SB 98   // Bs row stride (k-major), even -> aligned b64 loads

__global__ __launch_bounds__(256, 2)
void gemm_kernel(const float* __restrict__ h, float* __restrict__ out) {
    __shared__ __align__(16) float As[BK * SA];   // [k][m]
    __shared__ __align__(16) float Bs[BK * SB];   // [k][n]

    const int tid = threadIdx.x;
    const int m0  = blockIdx.x * BM;
    const int tx  = tid & 15;     // column group: cols tx*6 .. tx*6+5
    const int ty  = tid >> 4;     // row group:    rows ty*4 .. ty*4+3

    unsigned long long acc[4][3];
    #pragma unroll
    for (int i = 0; i < 4; i++)
        #pragma unroll
        for (int u = 0; u < 3; u++) acc[i][u] = 0ull;

    for (int k0 = 0; k0 < ND; k0 += BK) {
        // A tile: 64 rows x 32 k, transposed into smem
        #pragma unroll
        for (int r = 0; r < 2; r++) {
            int idx = tid + r * 256;
            int row = idx >> 3, c4 = idx & 7;
            float4 v = *(const float4*)(h + (size_t)(m0 + row) * ND + k0 + c4 * 4);
            As[(c4 * 4 + 0) * SA + row] = v.x;
            As[(c4 * 4 + 1) * SA + row] = v.y;
            As[(c4 * 4 + 2) * SA + row] = v.z;
            As[(c4 * 4 + 3) * SA + row] = v.w;
        }
        // B tile: 96 rows (cols of output) x 32 k, transposed into smem
        #pragma unroll
        for (int r = 0; r < 3; r++) {
            int idx = tid + r * 256;
            int n = idx >> 3, c4 = idx & 7;
            float4 v = *(const float4*)(g_Wc + (size_t)n * ND + k0 + c4 * 4);
            Bs[(c4 * 4 + 0) * SB + n] = v.x;
            Bs[(c4 * 4 + 1) * SB + n] = v.y;
            Bs[(c4 * 4 + 2) * SB + n] = v.z;
            Bs[(c4 * 4 + 3) * SB + n] = v.w;
        }
        __syncthreads();

        #pragma unroll
        for (int k = 0; k < BK; k++) {
            unsigned long long bv[3];
            #pragma unroll
            for (int u = 0; u < 3; u++)
                bv[u] = *(const unsigned long long*)(&Bs[k * SB + tx * 6 + 2 * u]);
            #pragma unroll
            for (int i = 0; i < 4; i++) {
                float av = As[k * SA + ty * 4 + i];
                unsigned long long ap = pack2(av, av);
                #pragma unroll
                for (int u = 0; u < 3; u++) fma2(acc[i][u], ap, bv[u]);
            }
        }
        __syncthreads();
    }

    // epilogue: add bias, split into act/time output regions
    float* out_time = out + ACT_ELEMS;
    #pragma unroll
    for (int i = 0; i < 4; i++) {
        size_t m = (size_t)m0 + ty * 4 + i;
        #pragma unroll
        for (int u = 0; u < 3; u++) {
            int col = tx * 6 + 2 * u;        // even; pairs never straddle col 64
            float2 v = unpack2(acc[i][u]);
            v.x += g_bc[col];
            v.y += g_bc[col + 1];
            if (col < N_ACT) {
                *(float2*)(out + m * N_ACT + col) = v;
            } else {
                *(float2*)(out_time + m * N_TIME + (col - N_ACT)) = v;
            }
        }
    }
}

// ---------------- kernel 4: retrieval/copy head (sparse, one block per label query) ----------------
__global__ __launch_bounds__(128)
void copy_kernel(const float* __restrict__ h, float* __restrict__ out,
                 const float* __restrict__ csa, const float* __restrict__ cst,
                 const float* __restrict__ cta, const float* __restrict__ ctt) {
    const int b  = blockIdx.y;
    const int qi = blockIdx.x;
    if (qi >= g_qcnt[b]) return;
    const int q   = g_qlist[b][qi];
    const int tid = threadIdx.x;          // 128 threads, 8 elems each

    __shared__ float s_acc[N_COLS];
    __shared__ float s_red[2][4];
    __shared__ float s_nq;
    if (tid < N_COLS) s_acc[tid] = 0.0f;

    const float* hq = h + ((size_t)b * NT_SEQ + q) * ND;
    float4 q0 = *(const float4*)(hq + tid * 8);
    float4 q1 = *(const float4*)(hq + tid * 8 + 4);

    float nq = q0.x*q0.x + q0.y*q0.y + q0.z*q0.z + q0.w*q0.w
             + q1.x*q1.x + q1.y*q1.y + q1.z*q1.z + q1.w*q1.w;
    #pragma unroll
    for (int o = 16; o; o >>= 1) nq += __shfl_down_sync(0xffffffffu, nq, o);
    if ((tid & 31) == 0) s_red[0][tid >> 5] = nq;
    __syncthreads();
    if (tid == 0) {
        float v = s_red[0][0] + s_red[0][1] + s_red[0][2] + s_red[0][3];
        s_nq = fmaxf(sqrtf(v), 1e-12f);
    }
    __syncthreads();
    const float norm_q = s_nq;
    const float tau_a = softplus_f(*cta);
    const float tau_t = softplus_f(*ctt);

    const int kc = g_kcnt[b];
    for (int j = 0; j < kc; j++) {
        int k = g_klist[b][j];
        if (k >= q) continue;             // strict past; uniform across block
        const float* hk = h + ((size_t)b * NT_SEQ + k) * ND;
        float4 k0 = *(const float4*)(hk + tid * 8);
        float4 k1 = *(const float4*)(hk + tid * 8 + 4);
        float dot = q0.x*k0.x + q0.y*k0.y + q0.z*k0.z + q0.w*k0.w
                  + q1.x*k1.x + q1.y*k1.y + q1.z*k1.z + q1.w*k1.w;
        float nk  = k0.x*k0.x + k0.y*k0.y + k0.z*k0.z + k0.w*k0.w
                  + k1.x*k1.x + k1.y*k1.y + k1.z*k1.z + k1.w*k1.w;
        #pragma unroll
        for (int o = 16; o; o >>= 1) {
            dot += __shfl_down_sync(0xffffffffu, dot, o);
            nk  += __shfl_down_sync(0xffffffffu, nk,  o);
        }
        if ((tid & 31) == 0) { s_red[0][tid >> 5] = dot; s_red[1][tid >> 5] = nk; }
        __syncthreads();
        if (tid == 0) {
            float d = s_red[0][0] + s_red[0][1] + s_red[0][2] + s_red[0][3];
            float n = s_red[1][0] + s_red[1][1] + s_red[1][2] + s_red[1][3];
            float sim = d / (fmaxf(sqrtf(n), 1e-12f) * norm_q);
            int cls = g_kcls[b][j];
            s_acc[cls] += sim * (cls < N_ACT ? tau_a : tau_t);
        }
        __syncthreads();
    }

    const float sca = softplus_f(*csa);
    const float sct = softplus_f(*cst);
    size_t m = (size_t)b * NT_SEQ + q;
    if (tid < N_ACT) {
        out[m * N_ACT + tid] += sca * s_acc[tid];
    } else if (tid < N_COLS) {
        float* out_time = out + ACT_ELEMS;
        out_time[m * N_TIME + (tid - N_ACT)] += sct * s_acc[tid];
    }
}

// ---------------- launch ----------------
extern "C" void kernel_launch(void* const* d_in, const int* in_sizes, int n_in,
                              void* d_out, int out_size) {
    const int*   tokens = (const int*)  d_in[0];
    const float* h      = (const float*)d_in[1];
    const float* E      = (const float*)d_in[2];
    const float* Wn     = (const float*)d_in[3];
    const float* bn     = (const float*)d_in[4];
    const float* Wt     = (const float*)d_in[5];
    const float* bt     = (const float*)d_in[6];
    const float* tsa    = (const float*)d_in[7];
    const float* tst    = (const float*)d_in[8];
    const float* csa    = (const float*)d_in[9];
    const float* cst    = (const float*)d_in[10];
    const float* cta    = (const float*)d_in[11];
    const float* ctt    = (const float*)d_in[12];
    float* out = (float*)d_out;

    wc_kernel<<<(N_COLS * ND + 255) / 256, 256>>>(E, Wn, bn, Wt, bt, tsa, tst);
    scan_kernel<<<NB, 64>>>(tokens);
    gemm_kernel<<<M_TOT / BM, 256>>>(h, out);
    copy_kernel<<<dim3(128, NB), 128>>>(h, out, csa, cst, cta, ctt);
}